// round 10
// baseline (speedup 1.0000x reference)
#include <cuda_runtime.h>
#include <cstdint>

// SphArr: complex orthonormal Y_l^m, l<4, over 524288 points.
// Out per point: 16 (l,m) x (re,im) = 32 floats (128B row).
// R10 (= R9 retry, infra timeout): direct-STG, no smem, no barriers, no TMA.
// 4 lanes cooperate per point: lane = (point, quarter q). Each lane computes
// the full intermediate set (4x redundant math; fma pipe has huge headroom)
// and stores v[2q], v[2q+1], so each warp's stores cover 1024B contiguous
// (8 full 128B lines -> 2 wavefronts/point). Streaming stores (evict-first)
// keep the 64MB write stream from thrashing X's L2 residency. Warps are fully
// independent streaming units; 4 unrolled passes give cross-pass ILP.

#define NPOINTS (8 * 256 * 256)
#define THREADS 256
#define PASSES 4
#define PTS_PER_BLOCK 256                       // 8 warps * 8 pts * 4 passes
#define NBLOCKS (NPOINTS / PTS_PER_BLOCK)       // 2048

__device__ __forceinline__ float4 sel4(bool c, float4 a, float4 b) {
    return make_float4(c ? a.x : b.x, c ? a.y : b.y, c ? a.z : b.z, c ? a.w : b.w);
}

__device__ __forceinline__ void stg_cg128(float4* p, float4 v) {
    asm volatile("st.global.cg.v4.f32 [%0], {%1, %2, %3, %4};"
                 :: "l"(p), "f"(v.x), "f"(v.y), "f"(v.z), "f"(v.w)
                 : "memory");
}

// ---- per-point math: 8 float4 components of the 32-float output row ----
__device__ __forceinline__ void sph_point(float x, float y, float z, float4 v[8]) {
    const float rho2 = fmaf(x, x, y * y);
    const float r2   = fmaf(z, z, rho2);
    const float rinv = rsqrtf(r2);
    const float ct   = z * rinv;                       // cos(theta)

    const bool  ok     = rho2 > 0.0f;
    const float rhoinv = ok ? rsqrtf(rho2) : 0.0f;
    const float st     = rho2 * rhoinv * rinv;         // sin(theta) = sqrt(rho2)/r
    const float c1 = ok ? x * rhoinv : 1.0f;
    const float s1 = y * rhoinv;
    const float c2 = c1 * c1 - s1 * s1;
    const float s2 = 2.0f * c1 * s1;
    const float c3 = c1 * c2 - s1 * s2;
    const float s3 = s1 * c2 + c1 * s2;

    const float ct2 = ct * ct;
    const float st2 = st * st;

    // Associated Legendre with Condon-Shortley phase (matches reference).
    const float b11 = 0.34549414947133547f * (-st);
    const float re1 = b11 * c1, im1 = b11 * s1;

    const float b21 = 0.25751613468215834f * (-3.0f * ct * st);
    const float re21 = b21 * c1, im21 = b21 * s1;
    const float b22 = 0.12875806734107764f * (3.0f * st2);
    const float re22 = b22 * c2, im22 = b22 * s2;

    const float b31 = 0.21545345607610053f * (-1.5f * st * (5.0f * ct2 - 1.0f));
    const float re31 = b31 * c1, im31 = b31 * s1;
    const float b32 = 0.06813236509755226f * (15.0f * ct * st2);
    const float re32 = b32 * c2, im32 = b32 * s2;
    const float b33 = 0.027814921575518937f * (-15.0f * st2 * st);
    const float re33 = b33 * c3, im33 = b33 * s3;

    const float y00 = 0.28209479177387814f;
    const float y10 = 0.48860251190291992f * ct;
    const float y20 = 0.63078313050504009f * 0.5f * (3.0f * ct2 - 1.0f);
    const float y30 = 0.74635266518023113f * 0.5f * ct * (5.0f * ct2 - 3.0f);

    v[0] = make_float4(y00, 0.0f, -re1, im1);
    v[1] = make_float4(y10, 0.0f, re1, im1);
    v[2] = make_float4(re22, -im22, -re21, im21);
    v[3] = make_float4(y20, 0.0f, re21, im21);
    v[4] = make_float4(re22, im22, -re33, im33);
    v[5] = make_float4(re32, -im32, -re31, im31);
    v[6] = make_float4(y30, 0.0f, re31, im31);
    v[7] = make_float4(re32, im32, re33, im33);
}

__global__ __launch_bounds__(THREADS) void sph_kernel(
    const float* __restrict__ X, float4* __restrict__ out) {
    const int lane = threadIdx.x & 31;
    const int warp = threadIdx.x >> 5;
    const int q = lane & 3;
    const bool qb0 = (q & 1) != 0;
    const bool qb1 = (q & 2) != 0;
    // Each warp owns 32 consecutive points, processed 8 per pass.
    const unsigned warp_base = blockIdx.x * (unsigned)PTS_PER_BLOCK + warp * 32u;

#pragma unroll
    for (int pass = 0; pass < PASSES; pass++) {
        const unsigned p = warp_base + pass * 8u + (lane >> 2);

        // 4 lanes per point load the same xyz (sector-merged; X stays cached).
        const float x = X[3u * p + 0];
        const float y = X[3u * p + 1];
        const float z = X[3u * p + 2];

        float4 v[8];
        sph_point(x, y, z, v);

        // Select this lane's two float4s: v[2q] and v[2q+1].
        const float4 a = sel4(qb0, sel4(qb1, v[6], v[2]), sel4(qb1, v[4], v[0]));
        const float4 b = sel4(qb0, sel4(qb1, v[7], v[3]), sel4(qb1, v[5], v[1]));

        // Warp-wide: addresses cover 8 full 128B lines, 1024B contiguous.
        float4* dst = out + (unsigned long long)p * 8ull + 2u * q;
        stg_cg128(dst, a);
        stg_cg128(dst + 1, b);
    }
}

extern "C" void kernel_launch(void* const* d_in, const int* in_sizes, int n_in,
                              void* d_out, int out_size) {
    const float* X = (const float*)d_in[0];
    sph_kernel<<<NBLOCKS, THREADS>>>(X, (float4*)d_out);
}

// round 13
// speedup vs baseline: 1.5551x; 1.5551x over previous
#include <cuda_runtime.h>
#include <cuda.h>
#include <cstdint>

// SphArr: complex orthonormal Y_l^m, l<4, over 524288 points.
// Out per point: 16 (l,m) x (re,im) = 32 floats (128B row).
// R13 (= R11/R12 retry, broker timeouts): many small single-shot blocks.
// 128 threads = 128 points, one 16KB SW128 buffer, one TMA tensor store,
// grid 4096. __launch_bounds__(128, 10) pins >=10 resident blocks/SM (~40
// phase-shifted warps): every latency (LDG, math chain, barrier, TMA drain)
// is hidden by neighbor blocks rather than intra-block pipelining.

#define NPOINTS (8 * 256 * 256)
#define THREADS 128
#define PTS_PER_BLOCK 128
#define NBLOCKS (NPOINTS / PTS_PER_BLOCK)       // 4096

// ---- per-point math: 8 float4 components of the 32-float output row ----
__device__ __forceinline__ void sph_point(float x, float y, float z, float4 v[8]) {
    const float rho2 = fmaf(x, x, y * y);
    const float r2   = fmaf(z, z, rho2);
    const float rinv = rsqrtf(r2);
    const float ct   = z * rinv;                       // cos(theta)

    const bool  ok     = rho2 > 0.0f;
    const float rhoinv = ok ? rsqrtf(rho2) : 0.0f;
    const float st     = rho2 * rhoinv * rinv;         // sin(theta) = sqrt(rho2)/r
    const float c1 = ok ? x * rhoinv : 1.0f;
    const float s1 = y * rhoinv;
    const float c2 = c1 * c1 - s1 * s1;
    const float s2 = 2.0f * c1 * s1;
    const float c3 = c1 * c2 - s1 * s2;
    const float s3 = s1 * c2 + c1 * s2;

    const float ct2 = ct * ct;
    const float st2 = st * st;

    // Associated Legendre with Condon-Shortley phase (matches reference).
    const float b11 = 0.34549414947133547f * (-st);
    const float re1 = b11 * c1, im1 = b11 * s1;

    const float b21 = 0.25751613468215834f * (-3.0f * ct * st);
    const float re21 = b21 * c1, im21 = b21 * s1;
    const float b22 = 0.12875806734107764f * (3.0f * st2);
    const float re22 = b22 * c2, im22 = b22 * s2;

    const float b31 = 0.21545345607610053f * (-1.5f * st * (5.0f * ct2 - 1.0f));
    const float re31 = b31 * c1, im31 = b31 * s1;
    const float b32 = 0.06813236509755226f * (15.0f * ct * st2);
    const float re32 = b32 * c2, im32 = b32 * s2;
    const float b33 = 0.027814921575518937f * (-15.0f * st2 * st);
    const float re33 = b33 * c3, im33 = b33 * s3;

    const float y00 = 0.28209479177387814f;
    const float y10 = 0.48860251190291992f * ct;
    const float y20 = 0.63078313050504009f * 0.5f * (3.0f * ct2 - 1.0f);
    const float y30 = 0.74635266518023113f * 0.5f * ct * (5.0f * ct2 - 3.0f);

    v[0] = make_float4(y00, 0.0f, -re1, im1);
    v[1] = make_float4(y10, 0.0f, re1, im1);
    v[2] = make_float4(re22, -im22, -re21, im21);
    v[3] = make_float4(y20, 0.0f, re21, im21);
    v[4] = make_float4(re22, im22, -re33, im33);
    v[5] = make_float4(re32, -im32, -re31, im31);
    v[6] = make_float4(y30, 0.0f, re31, im31);
    v[7] = make_float4(re32, im32, re33, im33);
}

// ---- fast path: single-shot 16KB SW128 tile + one TMA store per block ----
__global__ __launch_bounds__(THREADS, 10) void sph_kernel_tma(
    const __grid_constant__ CUtensorMap tmap,
    const float* __restrict__ X) {
    // 128 rows x 128B = 16KB, 1024B-aligned (SW128 atoms).
    __shared__ __align__(1024) float4 sm[128 * 8];

    const int tid = threadIdx.x;
    const int rot = tid & 7;
    const unsigned base = blockIdx.x * (unsigned)PTS_PER_BLOCK;
    const unsigned p = base + tid;

    const float x = X[3u * p + 0];
    const float y = X[3u * p + 1];
    const float z = X[3u * p + 2];

    float4 v[8];
    sph_point(x, y, z, v);

    // SW128 swizzled STS: row tid, slot q -> q ^ (tid&7); conflict-free.
    float4* row = sm + tid * 8;
    row[0 ^ rot] = v[0];
    row[1 ^ rot] = v[1];
    row[2 ^ rot] = v[2];
    row[3 ^ rot] = v[3];
    row[4 ^ rot] = v[4];
    row[5 ^ rot] = v[5];
    row[6 ^ rot] = v[6];
    row[7 ^ rot] = v[7];

    asm volatile("fence.proxy.async.shared::cta;" ::: "memory");
    __syncthreads();

    if (tid == 0) {
        uint32_t saddr;
        asm("{ .reg .u64 t; cvta.to.shared.u64 t, %1; cvt.u32.u64 %0, t; }"
            : "=r"(saddr) : "l"((const void*)sm));
        asm volatile(
            "cp.async.bulk.tensor.2d.global.shared::cta.tile.bulk_group "
            "[%0, {%1, %2}], [%3];"
            :: "l"(&tmap), "r"(0), "r"((int)base), "r"(saddr)
            : "memory");
        asm volatile("cp.async.bulk.commit_group;" ::: "memory");
        // Must not free smem (CTA exit) until the TMA has read it.
        asm volatile("cp.async.bulk.wait_group.read 0;" ::: "memory");
    }
}

// ---- fallback path: proven padded smem + coalesced STG ----
__global__ __launch_bounds__(128) void sph_kernel_stg(const float* __restrict__ X,
                                                      float4* __restrict__ out) {
    __shared__ float4 smf[256 * 9];
    const int tid = threadIdx.x;
    const unsigned base = blockIdx.x * 256u;
    const unsigned pa = base + tid;
    const unsigned pb = pa + 128;

    const float xa = X[3u * pa + 0], ya = X[3u * pa + 1], za = X[3u * pa + 2];
    const float xb = X[3u * pb + 0], yb = X[3u * pb + 1], zb = X[3u * pb + 2];

    float4 va[8], vb[8];
    sph_point(xa, ya, za, va);
    sph_point(xb, yb, zb, vb);

#pragma unroll
    for (int q = 0; q < 8; q++) smf[tid * 9 + q] = va[q];
#pragma unroll
    for (int q = 0; q < 8; q++) smf[(tid + 128) * 9 + q] = vb[q];

    __syncthreads();

    float4* dst = out + (unsigned long long)base * 8ull;
#pragma unroll
    for (int i = 0; i < 16; i++) {
        const int idx = tid + i * 128;
        dst[idx] = smf[(idx >> 3) * 9 + (idx & 7)];
    }
}

typedef CUresult (*EncodeFn)(
    CUtensorMap*, CUtensorMapDataType, cuuint32_t, void*,
    const cuuint64_t*, const cuuint64_t*, const cuuint32_t*, const cuuint32_t*,
    CUtensorMapInterleave, CUtensorMapSwizzle, CUtensorMapL2promotion,
    CUtensorMapFloatOOBfill);

extern "C" void kernel_launch(void* const* d_in, const int* in_sizes, int n_in,
                              void* d_out, int out_size) {
    const float* X = (const float*)d_in[0];

    void* fn = nullptr;
    cudaDriverEntryPointQueryResult qst = cudaDriverEntryPointSymbolNotFound;
    cudaError_t qerr = cudaGetDriverEntryPointByVersion(
        "cuTensorMapEncodeTiled", &fn, 12000, cudaEnableDefault, &qst);

    bool tma_ok = false;
    CUtensorMap tmap;
    if (qerr == cudaSuccess && qst == cudaDriverEntryPointSuccess && fn != nullptr) {
        EncodeFn encode = (EncodeFn)fn;
        cuuint64_t dims[2]    = {32, (cuuint64_t)NPOINTS};  // 32 f32 per row
        cuuint64_t strides[1] = {128};                      // 128B row stride
        cuuint32_t box[2]     = {32, 128};                  // 16KB tile
        cuuint32_t estr[2]    = {1, 1};
        CUresult r = encode(&tmap, CU_TENSOR_MAP_DATA_TYPE_FLOAT32, 2, d_out,
                            dims, strides, box, estr,
                            CU_TENSOR_MAP_INTERLEAVE_NONE,
                            CU_TENSOR_MAP_SWIZZLE_128B,
                            CU_TENSOR_MAP_L2_PROMOTION_L2_128B,
                            CU_TENSOR_MAP_FLOAT_OOB_FILL_NONE);
        tma_ok = (r == CUDA_SUCCESS);
    }

    if (tma_ok) {
        sph_kernel_tma<<<NBLOCKS, THREADS>>>(tmap, X);
    } else {
        sph_kernel_stg<<<NPOINTS / 256, 128>>>(X, (float4*)d_out);
    }
}